// round 3
// baseline (speedup 1.0000x reference)
#include <cuda_runtime.h>
#include <cuda_bf16.h>
#include <cstdint>

// Problem shapes (fixed by the dataset)
#define BB 64
#define QQ 512
#define CC 128
#define PP 2048
#define GG 256

// GEMM tiling
#define BM 128      // Q tile
#define BN 256      // G tile (full G -> attw read exactly once chip-wide)
#define BK 16       // K chunk (persons)
#define NTHREADS 512
#define A_PITCH 136 // BM + 8 bf16 pad (conflict-free ldmatrix)
#define B_PITCH 264 // BN + 8
#define L_PITCH 132 // CC + 4 (bf16 logits tile)

// scratch: per-(b,q) mean_c softplus(logits)
__device__ float g_SA[BB * QQ];

__device__ __forceinline__ float softplus_f(float x) {
    return fmaxf(x, 0.0f) + __logf(1.0f + __expf(-fabsf(x)));
}

// ---------------------------------------------------------------------------
// Kernel 1: SA[b,q] = (1/C) * sum_c softplus(logits[b,q,c]); warp per (b,q)
// ---------------------------------------------------------------------------
__global__ void sa_kernel(const float* __restrict__ logits) {
    int w = (blockIdx.x * blockDim.x + threadIdx.x) >> 5;
    int lane = threadIdx.x & 31;
    if (w >= BB * QQ) return;
    const float* row = logits + (size_t)w * CC;
    float s = 0.f;
#pragma unroll
    for (int i = 0; i < 4; i++) s += softplus_f(row[lane + 32 * i]);
#pragma unroll
    for (int o = 16; o; o >>= 1) s += __shfl_xor_sync(0xffffffffu, s, o);
    if (lane == 0) g_SA[w] = s * (1.0f / CC);
}

// ---------------------------------------------------------------------------
// Kernel 2: fused bf16 MMA GEMM + softplus(attw) + gather epilogue
// ---------------------------------------------------------------------------
struct SmemMain {
    __nv_bfloat16 As[2][BK][A_PITCH];  // [k][m], m contiguous
    __nv_bfloat16 Bs[2][BK][B_PITCH];  // [k][n], n contiguous
};
struct SmemEpi {
    __nv_bfloat16 slog[BM * L_PITCH];  // logits tile (bf16)
    int ids[GG];
};
union SmemU {
    SmemMain m;
    SmemEpi e;
};

__device__ __forceinline__ void ldsm4t(uint32_t& r0, uint32_t& r1, uint32_t& r2,
                                       uint32_t& r3, const void* p) {
    uint32_t addr = (uint32_t)__cvta_generic_to_shared(p);
    asm volatile(
        "ldmatrix.sync.aligned.m8n8.x4.trans.shared.b16 {%0,%1,%2,%3}, [%4];"
        : "=r"(r0), "=r"(r1), "=r"(r2), "=r"(r3)
        : "r"(addr));
}

__device__ __forceinline__ void mma_bf16(float* d, const uint32_t* a,
                                         const uint32_t* b) {
    asm volatile(
        "mma.sync.aligned.m16n8k16.row.col.f32.bf16.bf16.f32 "
        "{%0,%1,%2,%3}, {%4,%5,%6,%7}, {%8,%9}, {%0,%1,%2,%3};"
        : "+f"(d[0]), "+f"(d[1]), "+f"(d[2]), "+f"(d[3])
        : "r"(a[0]), "r"(a[1]), "r"(a[2]), "r"(a[3]), "r"(b[0]), "r"(b[1]));
}

__global__ void __launch_bounds__(NTHREADS, 1)
cost_kernel(const float* __restrict__ logits, const float* __restrict__ attw,
            const float* __restrict__ onehot, const int* __restrict__ ids,
            float* __restrict__ out) {
    __shared__ SmemU smem;
    __shared__ float s_sp[BM];

    const int tid = threadIdx.x;
    const int lane = tid & 31;
    const int warp = tid >> 5;
    const int wm = warp >> 2;  // 0..3  (32-row warp tile)
    const int wn = warp & 3;   // 0..3  (64-col warp tile)
    const int q0 = blockIdx.x * BM;
    const int b = blockIdx.y;

    if (tid < BM) s_sp[tid] = 0.0f;

    // global load assignments
    const int a_pl = tid >> 5;  // 0..15 : k row within chunk (A)
    const int a_fq = tid & 31;  // float4 index along Q
    const int b_pl = tid >> 6;  // 0..7  : k row within chunk (B), +8 second
    const int b_fg = tid & 63;  // float4 index along G

    const float4* aG = reinterpret_cast<const float4*>(attw + (size_t)b * PP * QQ + q0);
    const float4* bG = reinterpret_cast<const float4*>(onehot + (size_t)b * PP * GG);

    float acc[2][8][4];
#pragma unroll
    for (int i = 0; i < 2; i++)
#pragma unroll
        for (int j = 0; j < 8; j++)
#pragma unroll
            for (int k = 0; k < 4; k++) acc[i][j][k] = 0.0f;

    float sp_loc[4] = {0.f, 0.f, 0.f, 0.f};

    // prefetch chunk 0
    float4 ra = aG[(size_t)a_pl * (QQ / 4) + a_fq];
    float4 rb0 = bG[(size_t)b_pl * (GG / 4) + b_fg];
    float4 rb1 = bG[(size_t)(b_pl + 8) * (GG / 4) + b_fg];

    const int NK = PP / BK;  // 128
    for (int kc = 0; kc < NK; ++kc) {
        const int st = kc & 1;

        // ---- convert + store current chunk to SMEM, accumulate softplus(A)
        {
            __nv_bfloat162 lo = __floats2bfloat162_rn(ra.x, ra.y);
            __nv_bfloat162 hi = __floats2bfloat162_rn(ra.z, ra.w);
            uint2 v;
            v.x = *reinterpret_cast<uint32_t*>(&lo);
            v.y = *reinterpret_cast<uint32_t*>(&hi);
            *reinterpret_cast<uint2*>(&smem.m.As[st][a_pl][a_fq * 4]) = v;
            sp_loc[0] += softplus_f(ra.x);
            sp_loc[1] += softplus_f(ra.y);
            sp_loc[2] += softplus_f(ra.z);
            sp_loc[3] += softplus_f(ra.w);
        }
        {
            __nv_bfloat162 lo = __floats2bfloat162_rn(rb0.x, rb0.y);
            __nv_bfloat162 hi = __floats2bfloat162_rn(rb0.z, rb0.w);
            uint2 v;
            v.x = *reinterpret_cast<uint32_t*>(&lo);
            v.y = *reinterpret_cast<uint32_t*>(&hi);
            *reinterpret_cast<uint2*>(&smem.m.Bs[st][b_pl][b_fg * 4]) = v;
        }
        {
            __nv_bfloat162 lo = __floats2bfloat162_rn(rb1.x, rb1.y);
            __nv_bfloat162 hi = __floats2bfloat162_rn(rb1.z, rb1.w);
            uint2 v;
            v.x = *reinterpret_cast<uint32_t*>(&lo);
            v.y = *reinterpret_cast<uint32_t*>(&hi);
            *reinterpret_cast<uint2*>(&smem.m.Bs[st][b_pl + 8][b_fg * 4]) = v;
        }
        __syncthreads();

        // ---- prefetch next chunk (overlaps the MMA below)
        if (kc + 1 < NK) {
            const int p0 = (kc + 1) * BK;
            ra = aG[(size_t)(p0 + a_pl) * (QQ / 4) + a_fq];
            rb0 = bG[(size_t)(p0 + b_pl) * (GG / 4) + b_fg];
            rb1 = bG[(size_t)(p0 + b_pl + 8) * (GG / 4) + b_fg];
        }

        // ---- compute: one k16 step
        const int g = lane >> 3;           // submatrix group 0..3
        const int r = lane & 7;            // row within 8
        const int krow = r + ((g & 2) ? 8 : 0);
        const int coff = (g & 1) ? 8 : 0;

        uint32_t aF[2][4];
#pragma unroll
        for (int mt = 0; mt < 2; mt++) {
            const int m0 = wm * 32 + mt * 16 + coff;
            ldsm4t(aF[mt][0], aF[mt][1], aF[mt][2], aF[mt][3],
                   &smem.m.As[st][krow][m0]);
        }
        uint32_t bF[8][2];
#pragma unroll
        for (int ntp = 0; ntp < 4; ntp++) {
            const int n0 = wn * 64 + ntp * 16 + coff;
            uint32_t q0r, q1r, q2r, q3r;
            ldsm4t(q0r, q1r, q2r, q3r, &smem.m.Bs[st][krow][n0]);
            bF[2 * ntp + 0][0] = q0r;
            bF[2 * ntp + 1][0] = q1r;
            bF[2 * ntp + 0][1] = q2r;
            bF[2 * ntp + 1][1] = q3r;
        }
#pragma unroll
        for (int mt = 0; mt < 2; mt++)
#pragma unroll
            for (int nt = 0; nt < 8; nt++) mma_bf16(acc[mt][nt], aF[mt], bF[nt]);
    }

    __syncthreads();  // everyone done reading SmemMain before union re-use

    // softplus(attw) block reduction
#pragma unroll
    for (int j = 0; j < 4; j++) atomicAdd(&s_sp[a_fq * 4 + j], sp_loc[j]);

    // stage logits tile (bf16) + ids
    {
        const float4* lG =
            reinterpret_cast<const float4*>(logits + (size_t)(b * QQ + q0) * CC);
#pragma unroll
        for (int i = 0; i < 8; i++) {
            int idx = tid + i * NTHREADS;   // 0..4095
            int m = idx >> 5, fc = idx & 31;
            float4 v = lG[idx];
            __nv_bfloat162 lo = __floats2bfloat162_rn(v.x, v.y);
            __nv_bfloat162 hi = __floats2bfloat162_rn(v.z, v.w);
            uint2 u;
            u.x = *reinterpret_cast<uint32_t*>(&lo);
            u.y = *reinterpret_cast<uint32_t*>(&hi);
            *reinterpret_cast<uint2*>(&smem.e.slog[m * L_PITCH + fc * 4]) = u;
        }
        if (tid < GG) smem.e.ids[tid] = ids[b * GG + tid];
    }
    __syncthreads();

    // epilogue: cost = S - acc/P - logits_gather/C
    const float inv_p = 1.0f / PP;
    const float inv_c = 1.0f / CC;
#pragma unroll
    for (int mt = 0; mt < 2; mt++) {
        const int mbase = wm * 32 + mt * 16 + (lane >> 2);
#pragma unroll
        for (int rr = 0; rr < 2; rr++) {
            const int m = mbase + rr * 8;
            const float Sm = s_sp[m] * inv_p + g_SA[b * QQ + q0 + m];
            float* orow = out + (size_t)(b * QQ + q0 + m) * GG;
            const __nv_bfloat16* lrow = &smem.e.slog[m * L_PITCH];
#pragma unroll
            for (int nt = 0; nt < 8; nt++) {
                const int n = wn * 64 + nt * 8 + 2 * (lane & 3);
                const float d0 = acc[mt][nt][rr * 2 + 0];
                const float d1 = acc[mt][nt][rr * 2 + 1];
                const float gl0 = __bfloat162float(lrow[smem.e.ids[n]]);
                const float gl1 = __bfloat162float(lrow[smem.e.ids[n + 1]]);
                float2 o;
                o.x = Sm - d0 * inv_p - gl0 * inv_c;
                o.y = Sm - d1 * inv_p - gl1 * inv_c;
                *reinterpret_cast<float2*>(orow + n) = o;
            }
        }
    }
}

// ---------------------------------------------------------------------------
extern "C" void kernel_launch(void* const* d_in, const int* in_sizes, int n_in,
                              void* d_out, int out_size) {
    const float* logits = (const float*)d_in[0];  // [B,Q,C]
    const float* attw = (const float*)d_in[1];    // [B,P,Q]
    const float* onehot = (const float*)d_in[2];  // [B,P,G]
    const int* ids = (const int*)d_in[3];         // [B,G]
    float* out = (float*)d_out;                   // [B,Q,G]

    // SA: 32768 (b,q) warps, 8 warps per block
    sa_kernel<<<(BB * QQ) / 8, 256>>>(logits);

    dim3 grid(QQ / BM, BB);  // 4 x 64
    cost_kernel<<<grid, NTHREADS>>>(logits, attw, onehot, ids, out);
}

// round 4
// speedup vs baseline: 1.1083x; 1.1083x over previous
#include <cuda_runtime.h>
#include <cuda_bf16.h>
#include <cstdint>

// Problem shapes (fixed by the dataset)
#define BB 64
#define QQ 512
#define CC 128
#define PP 2048
#define GG 256

// GEMM tiling — BM halved vs R3 so TWO CTAs co-reside per SM (latency hiding)
#define BM 64       // Q tile
#define BN 256      // G tile (full G)
#define BK 16       // K chunk (persons)
#define NTHREADS 256
#define A_PITCH 72  // BM + 8 bf16 pad (conflict-free ldmatrix)
#define B_PITCH 264 // BN + 8
#define L_PITCH 132 // CC + 4 (bf16 logits tile)

// scratch: per-(b,q) mean_c softplus(logits)
__device__ float g_SA[BB * QQ];

__device__ __forceinline__ float softplus_f(float x) {
    return fmaxf(x, 0.0f) + __logf(1.0f + __expf(-fabsf(x)));
}

// ---------------------------------------------------------------------------
// Kernel 1: SA[b,q] = (1/C) * sum_c softplus(logits[b,q,c]); warp per (b,q)
// ---------------------------------------------------------------------------
__global__ void sa_kernel(const float* __restrict__ logits) {
    int w = (blockIdx.x * blockDim.x + threadIdx.x) >> 5;
    int lane = threadIdx.x & 31;
    if (w >= BB * QQ) return;
    const float* row = logits + (size_t)w * CC;
    float s = 0.f;
#pragma unroll
    for (int i = 0; i < 4; i++) s += softplus_f(row[lane + 32 * i]);
#pragma unroll
    for (int o = 16; o; o >>= 1) s += __shfl_xor_sync(0xffffffffu, s, o);
    if (lane == 0) g_SA[w] = s * (1.0f / CC);
}

// ---------------------------------------------------------------------------
// Kernel 2: fused bf16 MMA GEMM + softplus(attw) + gather epilogue
// ---------------------------------------------------------------------------
struct SmemMain {
    __nv_bfloat16 As[2][BK][A_PITCH];  // [k][m], m contiguous
    __nv_bfloat16 Bs[2][BK][B_PITCH];  // [k][n], n contiguous
};
struct SmemEpi {
    __nv_bfloat16 slog[BM * L_PITCH];  // logits tile (bf16)
    int ids[GG];
};
union SmemU {
    SmemMain m;
    SmemEpi e;
};

__device__ __forceinline__ void ldsm4t(uint32_t& r0, uint32_t& r1, uint32_t& r2,
                                       uint32_t& r3, const void* p) {
    uint32_t addr = (uint32_t)__cvta_generic_to_shared(p);
    asm volatile(
        "ldmatrix.sync.aligned.m8n8.x4.trans.shared.b16 {%0,%1,%2,%3}, [%4];"
        : "=r"(r0), "=r"(r1), "=r"(r2), "=r"(r3)
        : "r"(addr));
}

__device__ __forceinline__ void mma_bf16(float* d, const uint32_t* a,
                                         const uint32_t* b) {
    asm volatile(
        "mma.sync.aligned.m16n8k16.row.col.f32.bf16.bf16.f32 "
        "{%0,%1,%2,%3}, {%4,%5,%6,%7}, {%8,%9}, {%0,%1,%2,%3};"
        : "+f"(d[0]), "+f"(d[1]), "+f"(d[2]), "+f"(d[3])
        : "r"(a[0]), "r"(a[1]), "r"(a[2]), "r"(a[3]), "r"(b[0]), "r"(b[1]));
}

__global__ void __launch_bounds__(NTHREADS, 2)
cost_kernel(const float* __restrict__ logits, const float* __restrict__ attw,
            const float* __restrict__ onehot, const int* __restrict__ ids,
            float* __restrict__ out) {
    __shared__ SmemU smem;
    __shared__ float s_sp[BM];

    const int tid = threadIdx.x;
    const int lane = tid & 31;
    const int warp = tid >> 5;
    const int wm = warp >> 2;  // 0..1  (32-row warp tile)
    const int wn = warp & 3;   // 0..3  (64-col warp tile)
    const int q0 = blockIdx.x * BM;
    const int b = blockIdx.y;

    if (tid < BM) s_sp[tid] = 0.0f;

    // global load assignments
    const int a_pl = tid >> 4;  // 0..15 : k row within chunk (A)
    const int a_fq = tid & 15;  // float4 index along Q (16 float4 = 64 q)
    const int b_pl = tid >> 6;  // 0..3  : k row within chunk (B), rows +4,+8,+12
    const int b_fg = tid & 63;  // float4 index along G

    const float4* aG = reinterpret_cast<const float4*>(attw + (size_t)b * PP * QQ + q0);
    const float4* bG = reinterpret_cast<const float4*>(onehot + (size_t)b * PP * GG);

    float acc[2][8][4];
#pragma unroll
    for (int i = 0; i < 2; i++)
#pragma unroll
        for (int j = 0; j < 8; j++)
#pragma unroll
            for (int k = 0; k < 4; k++) acc[i][j][k] = 0.0f;

    float sp_loc[4] = {0.f, 0.f, 0.f, 0.f};

    // prefetch chunk 0
    float4 ra = aG[(size_t)a_pl * (QQ / 4) + a_fq];
    float4 rb[4];
#pragma unroll
    for (int j = 0; j < 4; j++)
        rb[j] = bG[(size_t)(b_pl + 4 * j) * (GG / 4) + b_fg];

    const int NK = PP / BK;  // 128
    for (int kc = 0; kc < NK; ++kc) {
        const int st = kc & 1;

        // ---- convert + store current chunk to SMEM, accumulate softplus(A)
        {
            __nv_bfloat162 lo = __floats2bfloat162_rn(ra.x, ra.y);
            __nv_bfloat162 hi = __floats2bfloat162_rn(ra.z, ra.w);
            uint2 v;
            v.x = *reinterpret_cast<uint32_t*>(&lo);
            v.y = *reinterpret_cast<uint32_t*>(&hi);
            *reinterpret_cast<uint2*>(&smem.m.As[st][a_pl][a_fq * 4]) = v;
            sp_loc[0] += softplus_f(ra.x);
            sp_loc[1] += softplus_f(ra.y);
            sp_loc[2] += softplus_f(ra.z);
            sp_loc[3] += softplus_f(ra.w);
        }
#pragma unroll
        for (int j = 0; j < 4; j++) {
            __nv_bfloat162 lo = __floats2bfloat162_rn(rb[j].x, rb[j].y);
            __nv_bfloat162 hi = __floats2bfloat162_rn(rb[j].z, rb[j].w);
            uint2 v;
            v.x = *reinterpret_cast<uint32_t*>(&lo);
            v.y = *reinterpret_cast<uint32_t*>(&hi);
            *reinterpret_cast<uint2*>(&smem.m.Bs[st][b_pl + 4 * j][b_fg * 4]) = v;
        }
        __syncthreads();

        // ---- prefetch next chunk (overlaps the MMA below)
        if (kc + 1 < NK) {
            const int p0 = (kc + 1) * BK;
            ra = aG[(size_t)(p0 + a_pl) * (QQ / 4) + a_fq];
#pragma unroll
            for (int j = 0; j < 4; j++)
                rb[j] = bG[(size_t)(p0 + b_pl + 4 * j) * (GG / 4) + b_fg];
        }

        // ---- compute: one k16 step
        const int g = lane >> 3;           // submatrix group 0..3
        const int r = lane & 7;            // row within 8
        const int krow = r + ((g & 2) ? 8 : 0);
        const int coff = (g & 1) ? 8 : 0;

        uint32_t aF[2][4];
#pragma unroll
        for (int mt = 0; mt < 2; mt++) {
            const int m0 = wm * 32 + mt * 16 + coff;
            ldsm4t(aF[mt][0], aF[mt][1], aF[mt][2], aF[mt][3],
                   &smem.m.As[st][krow][m0]);
        }
        uint32_t bF[8][2];
#pragma unroll
        for (int ntp = 0; ntp < 4; ntp++) {
            const int n0 = wn * 64 + ntp * 16 + coff;
            uint32_t q0r, q1r, q2r, q3r;
            ldsm4t(q0r, q1r, q2r, q3r, &smem.m.Bs[st][krow][n0]);
            bF[2 * ntp + 0][0] = q0r;
            bF[2 * ntp + 1][0] = q1r;
            bF[2 * ntp + 0][1] = q2r;
            bF[2 * ntp + 1][1] = q3r;
        }
#pragma unroll
        for (int mt = 0; mt < 2; mt++)
#pragma unroll
            for (int nt = 0; nt < 8; nt++) mma_bf16(acc[mt][nt], aF[mt], bF[nt]);
    }

    __syncthreads();  // everyone done reading SmemMain before union re-use

    // softplus(attw) block reduction (16 threads share each q column)
#pragma unroll
    for (int j = 0; j < 4; j++) atomicAdd(&s_sp[a_fq * 4 + j], sp_loc[j]);

    // stage logits tile (bf16) + ids
    {
        const float4* lG =
            reinterpret_cast<const float4*>(logits + (size_t)(b * QQ + q0) * CC);
#pragma unroll
        for (int i = 0; i < 8; i++) {
            int idx = tid + i * NTHREADS;   // 0..2047 (= BM*CC/4)
            int m = idx >> 5, fc = idx & 31;
            float4 v = lG[idx];
            __nv_bfloat162 lo = __floats2bfloat162_rn(v.x, v.y);
            __nv_bfloat162 hi = __floats2bfloat162_rn(v.z, v.w);
            uint2 u;
            u.x = *reinterpret_cast<uint32_t*>(&lo);
            u.y = *reinterpret_cast<uint32_t*>(&hi);
            *reinterpret_cast<uint2*>(&smem.e.slog[m * L_PITCH + fc * 4]) = u;
        }
        if (tid < GG) smem.e.ids[tid] = ids[b * GG + tid];
    }
    __syncthreads();

    // epilogue: cost = S - acc/P - logits_gather/C
    const float inv_p = 1.0f / PP;
    const float inv_c = 1.0f / CC;
#pragma unroll
    for (int mt = 0; mt < 2; mt++) {
        const int mbase = wm * 32 + mt * 16 + (lane >> 2);
#pragma unroll
        for (int rr = 0; rr < 2; rr++) {
            const int m = mbase + rr * 8;
            const float Sm = s_sp[m] * inv_p + g_SA[b * QQ + q0 + m];
            float* orow = out + (size_t)(b * QQ + q0 + m) * GG;
            const __nv_bfloat16* lrow = &smem.e.slog[m * L_PITCH];
#pragma unroll
            for (int nt = 0; nt < 8; nt++) {
                const int n = wn * 64 + nt * 8 + 2 * (lane & 3);
                const float d0 = acc[mt][nt][rr * 2 + 0];
                const float d1 = acc[mt][nt][rr * 2 + 1];
                const float gl0 = __bfloat162float(lrow[smem.e.ids[n]]);
                const float gl1 = __bfloat162float(lrow[smem.e.ids[n + 1]]);
                float2 o;
                o.x = Sm - d0 * inv_p - gl0 * inv_c;
                o.y = Sm - d1 * inv_p - gl1 * inv_c;
                *reinterpret_cast<float2*>(orow + n) = o;
            }
        }
    }
}

// ---------------------------------------------------------------------------
extern "C" void kernel_launch(void* const* d_in, const int* in_sizes, int n_in,
                              void* d_out, int out_size) {
    const float* logits = (const float*)d_in[0];  // [B,Q,C]
    const float* attw = (const float*)d_in[1];    // [B,P,Q]
    const float* onehot = (const float*)d_in[2];  // [B,P,G]
    const int* ids = (const int*)d_in[3];         // [B,G]
    float* out = (float*)d_out;                   // [B,Q,G]

    // SA: 32768 (b,q) warps, 8 warps per block
    sa_kernel<<<(BB * QQ) / 8, 256>>>(logits);

    dim3 grid(QQ / BM, BB);  // 8 x 64 = 512 CTAs, 2 per SM
    cost_kernel<<<grid, NTHREADS>>>(logits, attw, onehot, ids, out);
}

// round 5
// speedup vs baseline: 1.3157x; 1.1872x over previous
#include <cuda_runtime.h>
#include <cuda_bf16.h>
#include <cstdint>

// Problem shapes (fixed by the dataset)
#define BB 64
#define QQ 512
#define CC 128
#define PP 2048
#define GG 256

// Tiling
#define BM 64        // Q tile
#define BN 256       // G tile (full G)
#define BK 16        // K chunk (persons)
#define STAGES 6     // SMEM ring depth
#define NK (PP / BK) // 128 chunks
#define NTH 512      // 8 consumer warps + 8 producer warps
#define NGROUPS 4    // producer groups (2 warps = 64 threads each)
#define A_PITCH 72   // bf16 pitch, conflict-free ldmatrix
#define B_PITCH 264
#define L_PITCH 132  // bf16 logits tile pitch

// scratch: per-(b,q) mean_c softplus(logits)
__device__ float g_SA[BB * QQ];

__device__ __forceinline__ float softplus_f(float x) {
    return fmaxf(x, 0.0f) + __logf(1.0f + __expf(-fabsf(x)));
}

// ---------------------------------------------------------------------------
// mbarrier helpers
// ---------------------------------------------------------------------------
__device__ __forceinline__ uint32_t smem_u32(const void* p) {
    return (uint32_t)__cvta_generic_to_shared(p);
}

#define MBARRIER_INIT(addr, count)                                   \
    asm volatile("mbarrier.init.shared.b64 [%0], %1;" ::"r"(addr),   \
                 "r"((uint32_t)(count))                              \
                 : "memory")

#define MBARRIER_ARRIVE(addr)                                        \
    asm volatile("mbarrier.arrive.shared.b64 _, [%0];" ::"r"(addr)   \
                 : "memory")

#define MBARRIER_WAIT_PARITY(mbar_addr, phase_parity)                          \
    do {                                                                       \
        uint32_t _mbar = (uint32_t)(mbar_addr);                                \
        uint32_t _parity = (uint32_t)(phase_parity);                           \
        uint32_t _done;                                                        \
        asm volatile(                                                          \
            "{\n\t"                                                            \
            ".reg .pred p;\n\t"                                                \
            "mbarrier.try_wait.parity.acquire.cta.shared::cta.b64 p, [%1], "   \
            "%2;\n\t"                                                          \
            "selp.b32 %0, 1, 0, p;\n\t"                                        \
            "}"                                                                \
            : "=r"(_done)                                                      \
            : "r"(_mbar), "r"(_parity)                                         \
            : "memory");                                                       \
        if (!_done) {                                                          \
            asm volatile(                                                      \
                "{\n\t"                                                        \
                ".reg .pred P1;\n\t"                                           \
                "WAIT_LOOP_%=:\n\t"                                            \
                "mbarrier.try_wait.parity.acquire.cta.shared::cta.b64 P1, "    \
                "[%0], %1, 0x989680;\n\t"                                      \
                "@P1 bra.uni WAIT_DONE_%=;\n\t"                                \
                "bra.uni WAIT_LOOP_%=;\n\t"                                    \
                "WAIT_DONE_%=:\n\t"                                            \
                "}" ::"r"(_mbar),                                              \
                "r"(_parity)                                                   \
                : "memory");                                                   \
        }                                                                      \
    } while (0)

// ---------------------------------------------------------------------------
// Kernel 1: SA[b,q] = (1/C) * sum_c softplus(logits[b,q,c]); warp per (b,q)
// ---------------------------------------------------------------------------
__global__ void sa_kernel(const float* __restrict__ logits) {
    int w = (blockIdx.x * blockDim.x + threadIdx.x) >> 5;
    int lane = threadIdx.x & 31;
    if (w >= BB * QQ) return;
    const float* row = logits + (size_t)w * CC;
    float s = 0.f;
#pragma unroll
    for (int i = 0; i < 4; i++) s += softplus_f(row[lane + 32 * i]);
#pragma unroll
    for (int o = 16; o; o >>= 1) s += __shfl_xor_sync(0xffffffffu, s, o);
    if (lane == 0) g_SA[w] = s * (1.0f / CC);
}

// ---------------------------------------------------------------------------
// Kernel 2: warp-specialized producer/consumer GEMM + softplus + gather
// ---------------------------------------------------------------------------
struct Stage {
    __nv_bfloat16 A[BK][A_PITCH];  // [k][m], m contiguous
    __nv_bfloat16 B[BK][B_PITCH];  // [k][n], n contiguous
};
#define SMEM_DYN (STAGES * (int)sizeof(Stage))  // 6 * 10752 = 64512 B

__device__ __forceinline__ void ldsm4t(uint32_t& r0, uint32_t& r1, uint32_t& r2,
                                       uint32_t& r3, const void* p) {
    uint32_t addr = smem_u32(p);
    asm volatile(
        "ldmatrix.sync.aligned.m8n8.x4.trans.shared.b16 {%0,%1,%2,%3}, [%4];"
        : "=r"(r0), "=r"(r1), "=r"(r2), "=r"(r3)
        : "r"(addr));
}

__device__ __forceinline__ void mma_bf16(float* d, const uint32_t* a,
                                         const uint32_t* b) {
    asm volatile(
        "mma.sync.aligned.m16n8k16.row.col.f32.bf16.bf16.f32 "
        "{%0,%1,%2,%3}, {%4,%5,%6,%7}, {%8,%9}, {%0,%1,%2,%3};"
        : "+f"(d[0]), "+f"(d[1]), "+f"(d[2]), "+f"(d[3])
        : "r"(a[0]), "r"(a[1]), "r"(a[2]), "r"(a[3]), "r"(b[0]), "r"(b[1]));
}

extern "C" __global__ void __launch_bounds__(NTH, 1)
cost_kernel(const float* __restrict__ logits, const float* __restrict__ attw,
            const float* __restrict__ onehot, const int* __restrict__ ids,
            float* __restrict__ out) {
    extern __shared__ char dynsmem[];
    Stage* stages = reinterpret_cast<Stage*>(dynsmem);

    __shared__ alignas(8) unsigned long long bar_full[STAGES];
    __shared__ alignas(8) unsigned long long bar_empty[STAGES];
    __shared__ float s_sp[BM];
    __shared__ int s_ids[GG];

    const int tid = threadIdx.x;
    const int lane = tid & 31;
    const int warp = tid >> 5;
    const int q0 = blockIdx.x * BM;
    const int b = blockIdx.y;

    if (tid < BM) s_sp[tid] = 0.0f;
    if (tid == 0) {
#pragma unroll
        for (int s = 0; s < STAGES; s++) {
            MBARRIER_INIT(smem_u32(&bar_full[s]), 64);  // one producer group
            MBARRIER_INIT(smem_u32(&bar_empty[s]), 8);  // 8 consumer warps
        }
    }
    __syncthreads();

    if (warp < 8) {
        // ===================== CONSUMERS (warps 0..7) =====================
        const int wm = warp >> 2;  // 0..1 : 32-row warp tile
        const int wn = warp & 3;   // 0..3 : 64-col warp tile

        float acc[2][8][4];
#pragma unroll
        for (int i = 0; i < 2; i++)
#pragma unroll
            for (int j = 0; j < 8; j++)
#pragma unroll
                for (int k = 0; k < 4; k++) acc[i][j][k] = 0.0f;

        const int g = lane >> 3;
        const int r = lane & 7;
        const int krow = r + ((g & 2) ? 8 : 0);
        const int coff = (g & 1) ? 8 : 0;

        for (int kc = 0; kc < NK; ++kc) {
            const int st = kc % STAGES;
            const int fph = (kc / STAGES) & 1;
            MBARRIER_WAIT_PARITY(smem_u32(&bar_full[st]), fph);

            uint32_t aF[2][4];
#pragma unroll
            for (int mt = 0; mt < 2; mt++) {
                const int m0 = wm * 32 + mt * 16 + coff;
                ldsm4t(aF[mt][0], aF[mt][1], aF[mt][2], aF[mt][3],
                       &stages[st].A[krow][m0]);
            }
            uint32_t bF[8][2];
#pragma unroll
            for (int ntp = 0; ntp < 4; ntp++) {
                const int n0 = wn * 64 + ntp * 16 + coff;
                uint32_t q0r, q1r, q2r, q3r;
                ldsm4t(q0r, q1r, q2r, q3r, &stages[st].B[krow][n0]);
                bF[2 * ntp + 0][0] = q0r;
                bF[2 * ntp + 1][0] = q1r;
                bF[2 * ntp + 0][1] = q2r;
                bF[2 * ntp + 1][1] = q3r;
            }
#pragma unroll
            for (int mt = 0; mt < 2; mt++)
#pragma unroll
                for (int nt = 0; nt < 8; nt++) mma_bf16(acc[mt][nt], aF[mt], bF[nt]);

            // MMA issue requires all ldsm results -> safe to release the stage
            __syncwarp();
            if (lane == 0) MBARRIER_ARRIVE(smem_u32(&bar_empty[st]));
        }

        __syncthreads();  // join producers; s_sp complete; ring free for reuse

        // ---- stage logits tile (bf16) + ids (all threads help below via
        //      producers too, but consumers do their share here)
        {
            __nv_bfloat16* slog = reinterpret_cast<__nv_bfloat16*>(dynsmem);
            const float4* lG = reinterpret_cast<const float4*>(
                logits + (size_t)(b * QQ + q0) * CC);
#pragma unroll
            for (int i = 0; i < 4; i++) {
                int idx = tid + i * NTH;  // consumers cover 0..255,512..,1024..,1536..
                if (idx < BM * CC / 4) {
                    int m = idx >> 5, fc = idx & 31;
                    float4 v = lG[idx];
                    __nv_bfloat162 lo = __floats2bfloat162_rn(v.x, v.y);
                    __nv_bfloat162 hi = __floats2bfloat162_rn(v.z, v.w);
                    uint2 u;
                    u.x = *reinterpret_cast<uint32_t*>(&lo);
                    u.y = *reinterpret_cast<uint32_t*>(&hi);
                    *reinterpret_cast<uint2*>(&slog[m * L_PITCH + fc * 4]) = u;
                }
            }
            if (tid < GG) s_ids[tid] = ids[b * GG + tid];
        }
        __syncthreads();

        // ---- epilogue: cost = S - acc/P - logits_gather/C
        const float inv_p = 1.0f / PP;
        const float inv_c = 1.0f / CC;
        const __nv_bfloat16* slog = reinterpret_cast<__nv_bfloat16*>(dynsmem);
#pragma unroll
        for (int mt = 0; mt < 2; mt++) {
            const int mbase = wm * 32 + mt * 16 + (lane >> 2);
#pragma unroll
            for (int rr = 0; rr < 2; rr++) {
                const int m = mbase + rr * 8;
                const float Sm = s_sp[m] * inv_p + g_SA[b * QQ + q0 + m];
                float* orow = out + (size_t)(b * QQ + q0 + m) * GG;
                const __nv_bfloat16* lrow = &slog[m * L_PITCH];
#pragma unroll
                for (int nt = 0; nt < 8; nt++) {
                    const int n = wn * 64 + nt * 8 + 2 * (lane & 3);
                    const float d0 = acc[mt][nt][rr * 2 + 0];
                    const float d1 = acc[mt][nt][rr * 2 + 1];
                    const float gl0 = __bfloat162float(lrow[s_ids[n]]);
                    const float gl1 = __bfloat162float(lrow[s_ids[n + 1]]);
                    float2 o;
                    o.x = Sm - d0 * inv_p - gl0 * inv_c;
                    o.y = Sm - d1 * inv_p - gl1 * inv_c;
                    *reinterpret_cast<float2*>(orow + n) = o;
                }
            }
        }
    } else {
        // ===================== PRODUCERS (warps 8..15) =====================
        const int pg_tid = tid - 256;      // 0..255
        const int group = pg_tid >> 6;     // 0..3
        const int pt = pg_tid & 63;        // 0..63
        const int prow_a = pt >> 4;        // 0..3 : base A k-row
        const int pcol_a = pt & 15;        // A float4 col (q)

        const float4* aG =
            reinterpret_cast<const float4*>(attw + (size_t)b * PP * QQ + q0);
        const float4* bG =
            reinterpret_cast<const float4*>(onehot + (size_t)b * PP * GG);

        float sp_loc[4] = {0.f, 0.f, 0.f, 0.f};

        for (int t = 0; t < NK / NGROUPS; ++t) {
            const int kc = group + NGROUPS * t;
            const int st = kc % STAGES;
            const int eph = ((kc / STAGES) + 1) & 1;
            const int p0 = kc * BK;

            float4 ra[4], rb[16];
#pragma unroll
            for (int i = 0; i < 4; i++)
                ra[i] = aG[(size_t)(p0 + prow_a + 4 * i) * (QQ / 4) + pcol_a];
#pragma unroll
            for (int i = 0; i < 16; i++)
                rb[i] = bG[(size_t)(p0 + i) * (GG / 4) + pt];

            MBARRIER_WAIT_PARITY(smem_u32(&bar_empty[st]), eph);

#pragma unroll
            for (int i = 0; i < 4; i++) {
                sp_loc[0] += softplus_f(ra[i].x);
                sp_loc[1] += softplus_f(ra[i].y);
                sp_loc[2] += softplus_f(ra[i].z);
                sp_loc[3] += softplus_f(ra[i].w);
                __nv_bfloat162 lo = __floats2bfloat162_rn(ra[i].x, ra[i].y);
                __nv_bfloat162 hi = __floats2bfloat162_rn(ra[i].z, ra[i].w);
                uint2 v;
                v.x = *reinterpret_cast<uint32_t*>(&lo);
                v.y = *reinterpret_cast<uint32_t*>(&hi);
                *reinterpret_cast<uint2*>(
                    &stages[st].A[prow_a + 4 * i][pcol_a * 4]) = v;
            }
#pragma unroll
            for (int i = 0; i < 16; i++) {
                __nv_bfloat162 lo = __floats2bfloat162_rn(rb[i].x, rb[i].y);
                __nv_bfloat162 hi = __floats2bfloat162_rn(rb[i].z, rb[i].w);
                uint2 v;
                v.x = *reinterpret_cast<uint32_t*>(&lo);
                v.y = *reinterpret_cast<uint32_t*>(&hi);
                *reinterpret_cast<uint2*>(&stages[st].B[i][pt * 4]) = v;
            }
            MBARRIER_ARRIVE(smem_u32(&bar_full[st]));  // all 64 group threads
        }

        // softplus(attw) block reduction
#pragma unroll
        for (int j = 0; j < 4; j++) atomicAdd(&s_sp[4 * pcol_a + j], sp_loc[j]);

        __syncthreads();  // join consumers (ring now reusable)

        // help stage the logits tile
        {
            __nv_bfloat16* slog = reinterpret_cast<__nv_bfloat16*>(dynsmem);
            const float4* lG = reinterpret_cast<const float4*>(
                logits + (size_t)(b * QQ + q0) * CC);
#pragma unroll
            for (int i = 0; i < 4; i++) {
                int idx = tid + i * NTH;
                if (idx < BM * CC / 4) {
                    int m = idx >> 5, fc = idx & 31;
                    float4 v = lG[idx];
                    __nv_bfloat162 lo = __floats2bfloat162_rn(v.x, v.y);
                    __nv_bfloat162 hi = __floats2bfloat162_rn(v.z, v.w);
                    uint2 u;
                    u.x = *reinterpret_cast<uint32_t*>(&lo);
                    u.y = *reinterpret_cast<uint32_t*>(&hi);
                    *reinterpret_cast<uint2*>(&slog[m * L_PITCH + fc * 4]) = u;
                }
            }
        }
        __syncthreads();
        // producers hold no accumulators; done
    }
}

// ---------------------------------------------------------------------------
extern "C" void kernel_launch(void* const* d_in, const int* in_sizes, int n_in,
                              void* d_out, int out_size) {
    const float* logits = (const float*)d_in[0];  // [B,Q,C]
    const float* attw = (const float*)d_in[1];    // [B,P,Q]
    const float* onehot = (const float*)d_in[2];  // [B,P,G]
    const int* ids = (const int*)d_in[3];         // [B,G]
    float* out = (float*)d_out;                   // [B,Q,G]

    cudaFuncSetAttribute(cost_kernel, cudaFuncAttributeMaxDynamicSharedMemorySize,
                         SMEM_DYN);

    // SA: 32768 (b,q) warps, 8 warps per block
    sa_kernel<<<(BB * QQ) / 8, 256>>>(logits);

    dim3 grid(QQ / BM, BB);  // 8 x 64 = 512 CTAs (x-fastest: qtiles of a batch
                             // co-resident -> onehot L2 reuse)
    cost_kernel<<<grid, NTH, SMEM_DYN>>>(logits, attw, onehot, ids, out);
}